// round 1
// baseline (speedup 1.0000x reference)
#include <cuda_runtime.h>
#include <math.h>

// Problem constants
#define C_    16
#define L_    8192
#define E_    512
#define H_    256
#define M_    128
#define KTOP  30
#define SROWS (C_*(L_-1))          // 131056 valid rows (s = 1..L-1 per batch)
#define OUT_OFF ((size_t)SROWS * M_)

// Scratch for h = relu(x@W1 + b1): 131056 x 256 f32 = 134 MB (global, allocation-free)
__device__ float g_h[(size_t)SROWS * H_];

// ---------------------------------------------------------------------------
// Kernel 1: h = relu(xs @ W1 + b1)
// xs row r maps to x row (r + r/8191 + 1)  (skip s=0 of each batch)
// Tiling: BM=128, BN=128 (grid.y=2 covers H=256), BK=16, 256 threads, 8x8 micro
// ---------------------------------------------------------------------------
__global__ __launch_bounds__(256, 2) void k_gemm1(const float* __restrict__ x,
                                                  const float* __restrict__ W1,
                                                  const float* __restrict__ b1)
{
    __shared__ float As[16][132];   // transposed [k][row], padded
    __shared__ float Bs[16][128];   // [k][n]

    const int rb  = blockIdx.x * 128;
    const int nb  = blockIdx.y * 128;
    const int tid = threadIdx.x;
    const int tx  = tid & 15;       // col group
    const int ty  = tid >> 4;       // row group

    // A-load mapping: 128 rows x 4 float4s; thread -> (lrow, lkq), two rows each
    const int lkq  = tid & 3;
    const int lrow = tid >> 2;      // 0..63, also +64
    // B-load mapping: 16 rows x 32 float4s; thread -> (bk, bn), two rows each
    const int bk = tid >> 5;        // 0..7, also +8
    const int bn = (tid & 31) * 4;

    float acc[8][8];
#pragma unroll
    for (int i = 0; i < 8; i++)
#pragma unroll
        for (int j = 0; j < 8; j++) acc[i][j] = 0.f;

    for (int k0 = 0; k0 < E_; k0 += 16) {
#pragma unroll
        for (int h = 0; h < 2; ++h) {
            int r = rb + lrow + h * 64;
            float4 v = make_float4(0.f, 0.f, 0.f, 0.f);
            if (r < SROWS) {
                int src = r + r / (L_ - 1) + 1;
                v = *(const float4*)&x[(size_t)src * E_ + k0 + lkq * 4];
            }
            As[lkq * 4 + 0][lrow + h * 64] = v.x;
            As[lkq * 4 + 1][lrow + h * 64] = v.y;
            As[lkq * 4 + 2][lrow + h * 64] = v.z;
            As[lkq * 4 + 3][lrow + h * 64] = v.w;
        }
#pragma unroll
        for (int h = 0; h < 2; ++h) {
            int kk = bk + h * 8;
            *(float4*)&Bs[kk][bn] = *(const float4*)&W1[(size_t)(k0 + kk) * H_ + nb + bn];
        }
        __syncthreads();

#pragma unroll
        for (int k = 0; k < 16; ++k) {
            float a[8], b[8];
            *(float4*)&a[0] = *(const float4*)&As[k][ty * 4];
            *(float4*)&a[4] = *(const float4*)&As[k][64 + ty * 4];
            *(float4*)&b[0] = *(const float4*)&Bs[k][tx * 4];
            *(float4*)&b[4] = *(const float4*)&Bs[k][64 + tx * 4];
#pragma unroll
            for (int i = 0; i < 8; i++)
#pragma unroll
                for (int j = 0; j < 8; j++) acc[i][j] = fmaf(a[i], b[j], acc[i][j]);
        }
        __syncthreads();
    }

    // Epilogue: + b1, relu, store to g_h
#pragma unroll
    for (int i = 0; i < 8; i++) {
        int r = rb + ((i < 4) ? (ty * 4 + i) : (64 + ty * 4 + (i - 4)));
        if (r >= SROWS) continue;
#pragma unroll
        for (int jq = 0; jq < 2; jq++) {
            int n = nb + ((jq == 0) ? (tx * 4) : (64 + tx * 4));
            float4 o;
            o.x = fmaxf(acc[i][jq * 4 + 0] + b1[n + 0], 0.f);
            o.y = fmaxf(acc[i][jq * 4 + 1] + b1[n + 1], 0.f);
            o.z = fmaxf(acc[i][jq * 4 + 2] + b1[n + 2], 0.f);
            o.w = fmaxf(acc[i][jq * 4 + 3] + b1[n + 3], 0.f);
            *(float4*)&g_h[(size_t)r * H_ + n] = o;
        }
    }
}

// ---------------------------------------------------------------------------
// Kernel 2: logits = h @ W2 + b2, then gumbel-softmax + top-30 threshold +
//           sigmoid mask + padding mask, fused per row (one warp per row).
// Each block: W2 resident in smem (128 KB), 128 rows in 4 chunks of 32.
// ---------------------------------------------------------------------------
#define SM_W2  (H_ * M_)          // 32768 floats
#define SM_HT  (H_ * 36)          // transposed h chunk [k][row] padded to 36
#define SM_LG  (32 * 132)         // logits [row][m] padded
#define SMEM_FLOATS (SM_W2 + SM_HT + SM_LG)

__global__ __launch_bounds__(256) void k_gemm2(const int*   __restrict__ mask,
                                               const float* __restrict__ noise,
                                               const float* __restrict__ W2,
                                               const float* __restrict__ b2,
                                               float*       __restrict__ out,
                                               int write_kpm)
{
    extern __shared__ float sm[];
    float* w2s = sm;
    float* ht  = sm + SM_W2;
    float* lg  = sm + SM_W2 + SM_HT;

    const int tid  = threadIdx.x;
    const int lane = tid & 31;
    const int warp = tid >> 5;
    const int tn   = tid & 31;    // col group (cols tn*4..+3)
    const int tm   = tid >> 5;    // row group (rows tm*4..+3)

    // Load W2 into smem once
    for (int i = tid * 4; i < SM_W2; i += 256 * 4)
        *(float4*)&w2s[i] = *(const float4*)&W2[i];

    const int rowbase = blockIdx.x * 128;

    for (int chunk = 0; chunk < 4; ++chunk) {
        const int cb = rowbase + chunk * 32;
        __syncthreads();   // protect ht/lg reuse across chunks (also covers W2 first pass)

        // Load h chunk transposed: ht[k][row]
        {
            int row = tid >> 3;        // 0..31
            int kq0 = tid & 7;
            int r = cb + row;
#pragma unroll
            for (int it = 0; it < 8; ++it) {
                int kq = kq0 + it * 8; // 0..63 float4s along k
                float4 v = make_float4(0.f, 0.f, 0.f, 0.f);
                if (r < SROWS) v = *(const float4*)&g_h[(size_t)r * H_ + kq * 4];
                ht[(kq * 4 + 0) * 36 + row] = v.x;
                ht[(kq * 4 + 1) * 36 + row] = v.y;
                ht[(kq * 4 + 2) * 36 + row] = v.z;
                ht[(kq * 4 + 3) * 36 + row] = v.w;
            }
        }
        __syncthreads();

        // GEMM2: 32x128 = 4096 outputs; thread does 4x4 microtile over K=256
        float acc[4][4];
#pragma unroll
        for (int i = 0; i < 4; i++)
#pragma unroll
            for (int j = 0; j < 4; j++) acc[i][j] = 0.f;

#pragma unroll 4
        for (int k = 0; k < H_; ++k) {
            float4 a = *(const float4*)&ht[k * 36 + tm * 4];       // broadcast in warp
            float4 b = *(const float4*)&w2s[k * M_ + tn * 4];      // conflict-free
            float av[4] = {a.x, a.y, a.z, a.w};
            float bv[4] = {b.x, b.y, b.z, b.w};
#pragma unroll
            for (int i = 0; i < 4; i++)
#pragma unroll
                for (int j = 0; j < 4; j++) acc[i][j] = fmaf(av[i], bv[j], acc[i][j]);
        }

        // Store logits (+b2) to smem
#pragma unroll
        for (int i = 0; i < 4; i++) {
            float4 o;
            o.x = acc[i][0] + b2[tn * 4 + 0];
            o.y = acc[i][1] + b2[tn * 4 + 1];
            o.z = acc[i][2] + b2[tn * 4 + 2];
            o.w = acc[i][3] + b2[tn * 4 + 3];
            *(float4*)&lg[(tm * 4 + i) * 132 + tn * 4] = o;
        }
        __syncthreads();

        // Epilogue: warp w handles local rows w*4 .. w*4+3
        for (int i = 0; i < 4; i++) {
            int rl = warp * 4 + i;
            int r = cb + rl;
            if (r >= SROWS) continue;

            int c  = r / (L_ - 1);
            int km = mask[r + c + 1];          // key_padding_mask[:,1:]
            if (write_kpm && lane == 0) out[OUT_OFF + r] = km ? 1.0f : 0.0f;

            if (km) {
#pragma unroll
                for (int j = 0; j < 4; j++)
                    out[(size_t)r * M_ + lane + 32 * j] = 0.0f;
                continue;
            }

            // perturbed = logits + gumbel (TAU = TEMP = 1)
            float z[4];
#pragma unroll
            for (int j = 0; j < 4; j++) {
                float u = noise[(size_t)r * M_ + lane + 32 * j];
                float g = -logf(-logf(u + 1e-20f) + 1e-20f);
                z[j] = lg[rl * 132 + lane + 32 * j] + g;
            }
            // softmax
            float mx = fmaxf(fmaxf(z[0], z[1]), fmaxf(z[2], z[3]));
#pragma unroll
            for (int s = 16; s; s >>= 1) mx = fmaxf(mx, __shfl_xor_sync(0xffffffffu, mx, s));
            float p[4], ssum = 0.f;
#pragma unroll
            for (int j = 0; j < 4; j++) { p[j] = expf(z[j] - mx); ssum += p[j]; }
#pragma unroll
            for (int s = 16; s; s >>= 1) ssum += __shfl_xor_sync(0xffffffffu, ssum, s);
            float inv = 1.0f / ssum;
#pragma unroll
            for (int j = 0; j < 4; j++) p[j] *= inv;

            // exact top-30: 30 argmax extractions with unique-index removal
            float q[4] = {p[0], p[1], p[2], p[3]};
            float th = 0.f;
            for (int t = 0; t < KTOP; t++) {
                unsigned long long key = 0ull;
#pragma unroll
                for (int j = 0; j < 4; j++) {
                    if (q[j] >= 0.f) {
                        unsigned long long kk =
                            ((unsigned long long)__float_as_uint(q[j]) << 32) |
                            (unsigned)((j << 5) | lane);
                        if (kk > key) key = kk;
                    }
                }
#pragma unroll
                for (int s = 16; s; s >>= 1) {
                    unsigned long long o = __shfl_xor_sync(0xffffffffu, key, s);
                    if (o > key) key = o;
                }
                th = __uint_as_float((unsigned)(key >> 32));
                unsigned id = (unsigned)(key & 0xffffffffu);
                if ((id & 31u) == (unsigned)lane) q[id >> 5] = -1.0f;
            }

            // out = p * sigmoid((p - th)/0.01)
#pragma unroll
            for (int j = 0; j < 4; j++) {
                float sg = 1.0f / (1.0f + expf((th - p[j]) * 100.0f));
                out[(size_t)r * M_ + lane + 32 * j] = p[j] * sg;
            }
        }
    }
}

// ---------------------------------------------------------------------------
extern "C" void kernel_launch(void* const* d_in, const int* in_sizes, int n_in,
                              void* d_out, int out_size)
{
    const float* x     = (const float*)d_in[0];
    const int*   mask  = (const int*)  d_in[1];
    const float* noise = (const float*)d_in[2];
    const float* W1    = (const float*)d_in[3];
    const float* b1    = (const float*)d_in[4];
    const float* W2    = (const float*)d_in[5];
    const float* b2    = (const float*)d_in[6];
    float* out = (float*)d_out;

    int write_kpm = ((size_t)out_size >= OUT_OFF + SROWS) ? 1 : 0;

    cudaFuncSetAttribute(k_gemm2, cudaFuncAttributeMaxDynamicSharedMemorySize,
                         SMEM_FLOATS * sizeof(float));

    k_gemm1<<<dim3((SROWS + 127) / 128, 2), 256>>>(x, W1, b1);
    k_gemm2<<<(SROWS + 127) / 128, 256, SMEM_FLOATS * sizeof(float)>>>(
        mask, noise, W2, b2, out, write_kpm);
}

// round 5
// speedup vs baseline: 2.0834x; 2.0834x over previous
#include <cuda_runtime.h>
#include <cuda_bf16.h>
#include <math.h>
#include <stdint.h>

#define C_    16
#define L_    8192
#define E_    512
#define H_    256
#define M_    128
#define KTOP  30
#define SROWS (C_*(L_-1))          // 131056
#define OUT_OFF ((size_t)SROWS * M_)

// Global scratch (allocation-free)
__device__ __align__(16) uint32_t g_hp[(size_t)SROWS * H_];   // h packed (lo16<<16)|hi16, 134 MB
__device__ __align__(16) __nv_bfloat16 g_w1hi[E_ * H_];       // W1 [k][n] hi
__device__ __align__(16) __nv_bfloat16 g_w1lo[E_ * H_];
__device__ __align__(16) __nv_bfloat16 g_w2hi[H_ * M_];       // W2 [k][n] hi
__device__ __align__(16) __nv_bfloat16 g_w2lo[H_ * M_];

// ---------------------------------------------------------------------------
__device__ __forceinline__ uint32_t smem_u32(const void* p) {
    uint32_t a;
    asm("{ .reg .u64 t; cvta.to.shared.u64 t, %1; cvt.u32.u64 %0, t; }" : "=r"(a) : "l"(p));
    return a;
}
__device__ __forceinline__ void ldsm_x4(uint32_t* r, uint32_t addr) {
    asm volatile("ldmatrix.sync.aligned.m8n8.x4.shared.b16 {%0,%1,%2,%3}, [%4];"
        : "=r"(r[0]), "=r"(r[1]), "=r"(r[2]), "=r"(r[3]) : "r"(addr));
}
__device__ __forceinline__ void ldsm_x4t(uint32_t* r, uint32_t addr) {
    asm volatile("ldmatrix.sync.aligned.m8n8.x4.trans.shared.b16 {%0,%1,%2,%3}, [%4];"
        : "=r"(r[0]), "=r"(r[1]), "=r"(r[2]), "=r"(r[3]) : "r"(addr));
}
__device__ __forceinline__ void mma16816(float* d, const uint32_t* a, const uint32_t* b) {
    asm volatile("mma.sync.aligned.m16n8k16.row.col.f32.bf16.bf16.f32 "
        "{%0,%1,%2,%3}, {%4,%5,%6,%7}, {%8,%9}, {%0,%1,%2,%3};"
        : "+f"(d[0]), "+f"(d[1]), "+f"(d[2]), "+f"(d[3])
        : "r"(a[0]), "r"(a[1]), "r"(a[2]), "r"(a[3]), "r"(b[0]), "r"(b[1]));
}
__device__ __forceinline__ void split1(float v, uint16_t& hi, uint16_t& lo) {
    __nv_bfloat16 h = __float2bfloat16(v);
    hi = __bfloat16_as_ushort(h);
    lo = __bfloat16_as_ushort(__float2bfloat16(v - __bfloat162float(h)));
}

// ---------------------------------------------------------------------------
// k_prep: split W1, W2 ([k][n] layout preserved) into bf16 hi/lo
// ---------------------------------------------------------------------------
__global__ void k_prep(const float* __restrict__ W1, const float* __restrict__ W2) {
    int i = blockIdx.x * 256 + threadIdx.x;
    if (i < E_ * H_) {
        uint16_t h, l; split1(W1[i], h, l);
        g_w1hi[i] = __ushort_as_bfloat16(h);
        g_w1lo[i] = __ushort_as_bfloat16(l);
    }
    if (i < H_ * M_) {
        uint16_t h, l; split1(W2[i], h, l);
        g_w2hi[i] = __ushort_as_bfloat16(h);
        g_w2lo[i] = __ushort_as_bfloat16(l);
    }
}

// ---------------------------------------------------------------------------
// Shared GEMM geometry: CTA tile 128x128, BK=32, 8 warps (2x4), warp 64x32.
// A smem: [128][40] bf16 (pad 8), B smem: [32][136] bf16 (pad 8).
// ---------------------------------------------------------------------------
#define LDA 40
#define LDB 136
#define ASH 0
#define ASL 10240
#define BSH 20480
#define BSL 29184
#define STAGE_BYTES 37888

// ---------------------------------------------------------------------------
// k1: h = relu(xs @ W1 + b1), split-3 bf16 mma.sync. grid (2 nblk, 1024 rblk)
// ---------------------------------------------------------------------------
__global__ __launch_bounds__(256, 2) void k1(const float* __restrict__ x,
                                             const float* __restrict__ b1) {
    extern __shared__ char smem[];
    const uint32_t sb = smem_u32(smem);
    const int tid = threadIdx.x, wid = tid >> 5, lane = tid & 31;
    const int rb = blockIdx.y * 128;
    const int nb = blockIdx.x * 128;
    const int wm = (wid >> 2) * 64, wn = (wid & 3) * 32;

    float acc[4][4][4];
#pragma unroll
    for (int a = 0; a < 4; a++)
#pragma unroll
        for (int b = 0; b < 4; b++)
#pragma unroll
            for (int c = 0; c < 4; c++) acc[a][b][c] = 0.f;

    for (int it = 0; it < E_ / 32; ++it) {
        const int k0 = it * 32;
        __syncthreads();
        // stage A: 128 rows x 32 cols fp32 -> hi/lo bf16
        for (int i = tid; i < 1024; i += 256) {
            int row = i >> 3, q = i & 7;
            int r = rb + row;
            float4 v = make_float4(0.f, 0.f, 0.f, 0.f);
            if (r < SROWS) {
                int src = r + r / (L_ - 1) + 1;
                v = *(const float4*)&x[(size_t)src * E_ + k0 + q * 4];
            }
            uint16_t h0,l0,h1,l1,h2,l2,h3,l3;
            split1(v.x,h0,l0); split1(v.y,h1,l1); split1(v.z,h2,l2); split1(v.w,h3,l3);
            uint2 hv = make_uint2((uint32_t)h0 | ((uint32_t)h1 << 16),
                                  (uint32_t)h2 | ((uint32_t)h3 << 16));
            uint2 lv = make_uint2((uint32_t)l0 | ((uint32_t)l1 << 16),
                                  (uint32_t)l2 | ((uint32_t)l3 << 16));
            *(uint2*)(smem + ASH + row * (LDA*2) + q * 8) = hv;
            *(uint2*)(smem + ASL + row * (LDA*2) + q * 8) = lv;
        }
        // stage B: 32 k x 128 n, prepped bf16
        for (int i = tid; i < 512; i += 256) {
            int k = i >> 4, nq = i & 15;
            size_t gsrc = (size_t)(k0 + k) * H_ + nb + nq * 8;
            *(uint4*)(smem + BSH + k * (LDB*2) + nq * 16) = *(const uint4*)&g_w1hi[gsrc];
            *(uint4*)(smem + BSL + k * (LDB*2) + nq * 16) = *(const uint4*)&g_w1lo[gsrc];
        }
        __syncthreads();

#pragma unroll
        for (int ks = 0; ks < 2; ++ks) {
            const int kk = ks * 16;
            uint32_t ah[4][4], al[4][4], bh[2][4], bl[2][4];
            const int arow = lane & 15, acol = kk + ((lane >> 4) << 3);
#pragma unroll
            for (int mf = 0; mf < 4; ++mf) {
                uint32_t off = (uint32_t)((wm + mf * 16 + arow) * LDA + acol) * 2;
                ldsm_x4(ah[mf], sb + ASH + off);
                ldsm_x4(al[mf], sb + ASL + off);
            }
            const int brow = kk + (lane & 7) + (((lane >> 3) & 1) << 3);
            const int bcol = wn + ((lane >> 4) << 3);
#pragma unroll
            for (int nn = 0; nn < 2; ++nn) {
                uint32_t off = (uint32_t)(brow * LDB + bcol + nn * 16) * 2;
                ldsm_x4t(bh[nn], sb + BSH + off);
                ldsm_x4t(bl[nn], sb + BSL + off);
            }
#pragma unroll
            for (int mf = 0; mf < 4; ++mf)
#pragma unroll
                for (int nf = 0; nf < 4; ++nf) {
                    const uint32_t* bhf = &bh[nf >> 1][(nf & 1) * 2];
                    const uint32_t* blf = &bl[nf >> 1][(nf & 1) * 2];
                    mma16816(acc[mf][nf], ah[mf], bhf);
                    mma16816(acc[mf][nf], al[mf], bhf);
                    mma16816(acc[mf][nf], ah[mf], blf);
                }
        }
    }

    // epilogue: +b1, relu, split, packed store
#pragma unroll
    for (int mf = 0; mf < 4; ++mf) {
        int r0 = rb + wm + mf * 16 + (lane >> 2);
#pragma unroll
        for (int half = 0; half < 2; ++half) {
            int r = r0 + half * 8;
            if (r >= SROWS) continue;
#pragma unroll
            for (int nf = 0; nf < 4; ++nf) {
                int c0 = nb + wn + nf * 8 + ((lane & 3) << 1);
                float v0 = fmaxf(acc[mf][nf][half*2+0] + __ldg(&b1[c0]),   0.f);
                float v1 = fmaxf(acc[mf][nf][half*2+1] + __ldg(&b1[c0+1]), 0.f);
                uint16_t h0,l0,h1,l1;
                split1(v0,h0,l0); split1(v1,h1,l1);
                uint2 pv = make_uint2((uint32_t)h0 | ((uint32_t)l0 << 16),
                                      (uint32_t)h1 | ((uint32_t)l1 << 16));
                *(uint2*)&g_hp[(size_t)r * H_ + c0] = pv;
            }
        }
    }
}

// ---------------------------------------------------------------------------
// k2: logits = h @ W2 + b2 (split-3 mma.sync) + fused gumbel/softmax/top-30
// ---------------------------------------------------------------------------
#define LGS 132
#define K2_SMEM (128 * LGS * 4)    // 67584 >= STAGE_BYTES, overlaid

__global__ __launch_bounds__(256, 2) void k2(const int*   __restrict__ mask,
                                             const float* __restrict__ noise,
                                             const float* __restrict__ b2,
                                             float*       __restrict__ out,
                                             int write_kpm) {
    extern __shared__ char smem[];
    const uint32_t sb = smem_u32(smem);
    const int tid = threadIdx.x, wid = tid >> 5, lane = tid & 31;
    const int rb = blockIdx.x * 128;
    const int wm = (wid >> 2) * 64, wn = (wid & 3) * 32;

    float acc[4][4][4];
#pragma unroll
    for (int a = 0; a < 4; a++)
#pragma unroll
        for (int b = 0; b < 4; b++)
#pragma unroll
            for (int c = 0; c < 4; c++) acc[a][b][c] = 0.f;

    for (int it = 0; it < H_ / 32; ++it) {
        const int k0 = it * 32;
        __syncthreads();
        // stage A from packed h
        for (int i = tid; i < 1024; i += 256) {
            int row = i >> 3, q = i & 7;
            int r = rb + row;
            uint4 v = make_uint4(0u, 0u, 0u, 0u);
            if (r < SROWS) v = *(const uint4*)&g_hp[(size_t)r * H_ + k0 + q * 4];
            uint2 hv = make_uint2(__byte_perm(v.x, v.y, 0x5410), __byte_perm(v.z, v.w, 0x5410));
            uint2 lv = make_uint2(__byte_perm(v.x, v.y, 0x7632), __byte_perm(v.z, v.w, 0x7632));
            *(uint2*)(smem + ASH + row * (LDA*2) + q * 8) = hv;
            *(uint2*)(smem + ASL + row * (LDA*2) + q * 8) = lv;
        }
        // stage B (W2 hi/lo, n=128)
        for (int i = tid; i < 512; i += 256) {
            int k = i >> 4, nq = i & 15;
            size_t gsrc = (size_t)(k0 + k) * M_ + nq * 8;
            *(uint4*)(smem + BSH + k * (LDB*2) + nq * 16) = *(const uint4*)&g_w2hi[gsrc];
            *(uint4*)(smem + BSL + k * (LDB*2) + nq * 16) = *(const uint4*)&g_w2lo[gsrc];
        }
        __syncthreads();

#pragma unroll
        for (int ks = 0; ks < 2; ++ks) {
            const int kk = ks * 16;
            uint32_t ah[4][4], al[4][4], bh[2][4], bl[2][4];
            const int arow = lane & 15, acol = kk + ((lane >> 4) << 3);
#pragma unroll
            for (int mf = 0; mf < 4; ++mf) {
                uint32_t off = (uint32_t)((wm + mf * 16 + arow) * LDA + acol) * 2;
                ldsm_x4(ah[mf], sb + ASH + off);
                ldsm_x4(al[mf], sb + ASL + off);
            }
            const int brow = kk + (lane & 7) + (((lane >> 3) & 1) << 3);
            const int bcol = wn + ((lane >> 4) << 3);
#pragma unroll
            for (int nn = 0; nn < 2; ++nn) {
                uint32_t off = (uint32_t)(brow * LDB + bcol + nn * 16) * 2;
                ldsm_x4t(bh[nn], sb + BSH + off);
                ldsm_x4t(bl[nn], sb + BSL + off);
            }
#pragma unroll
            for (int mf = 0; mf < 4; ++mf)
#pragma unroll
                for (int nf = 0; nf < 4; ++nf) {
                    const uint32_t* bhf = &bh[nf >> 1][(nf & 1) * 2];
                    const uint32_t* blf = &bl[nf >> 1][(nf & 1) * 2];
                    mma16816(acc[mf][nf], ah[mf], bhf);
                    mma16816(acc[mf][nf], al[mf], bhf);
                    mma16816(acc[mf][nf], ah[mf], blf);
                }
        }
    }
    __syncthreads();

    // logits (+b2) -> smem
    float* lg = (float*)smem;
#pragma unroll
    for (int mf = 0; mf < 4; ++mf) {
        int rl0 = wm + mf * 16 + (lane >> 2);
#pragma unroll
        for (int half = 0; half < 2; ++half) {
            int rl = rl0 + half * 8;
#pragma unroll
            for (int nf = 0; nf < 4; ++nf) {
                int c0 = wn + nf * 8 + ((lane & 3) << 1);
                lg[rl * LGS + c0]     = acc[mf][nf][half*2+0] + __ldg(&b2[c0]);
                lg[rl * LGS + c0 + 1] = acc[mf][nf][half*2+1] + __ldg(&b2[c0+1]);
            }
        }
    }
    __syncthreads();

    // fused epilogue: warp wid handles rows wid*16 .. +15
    for (int i = 0; i < 16; ++i) {
        int rl = wid * 16 + i;
        int r = rb + rl;
        if (r >= SROWS) continue;

        int cidx = r / (L_ - 1);
        int km = mask[r + cidx + 1];
        if (write_kpm && lane == 0) out[OUT_OFF + r] = km ? 1.0f : 0.0f;
        if (km) {
#pragma unroll
            for (int j = 0; j < 4; ++j) out[(size_t)r * M_ + lane + 32 * j] = 0.0f;
            continue;
        }

        float z[4];
#pragma unroll
        for (int j = 0; j < 4; ++j) {
            float u = noise[(size_t)r * M_ + lane + 32 * j];
            float inner = logf(u + 1e-20f);
            float g = -__logf(-inner + 1e-20f);
            z[j] = lg[rl * LGS + lane + 32 * j] + g;
        }
        float mx = fmaxf(fmaxf(z[0], z[1]), fmaxf(z[2], z[3]));
#pragma unroll
        for (int s = 16; s; s >>= 1) mx = fmaxf(mx, __shfl_xor_sync(0xffffffffu, mx, s));
        float p[4], ssum = 0.f;
#pragma unroll
        for (int j = 0; j < 4; ++j) { p[j] = __expf(z[j] - mx); ssum += p[j]; }
#pragma unroll
        for (int s = 16; s; s >>= 1) ssum += __shfl_xor_sync(0xffffffffu, ssum, s);
        float inv = 1.0f / ssum;
#pragma unroll
        for (int j = 0; j < 4; ++j) p[j] *= inv;

        // exact 30th-largest via bit-pattern bisection
        unsigned lo = 0u, hi = 0x3F800000u;
        for (int itb = 0; itb < 31; ++itb) {
            unsigned mid = lo + ((hi - lo + 1) >> 1);
            float t = __uint_as_float(mid);
            int cgt = (p[0] >= t) + (p[1] >= t) + (p[2] >= t) + (p[3] >= t);
            int tot = __reduce_add_sync(0xffffffffu, cgt);
            if (tot >= KTOP) lo = mid; else hi = mid - 1;
        }
        float th = __uint_as_float(lo);

#pragma unroll
        for (int j = 0; j < 4; ++j) {
            float sg = 1.0f / (1.0f + __expf((th - p[j]) * 100.0f));
            out[(size_t)r * M_ + lane + 32 * j] = p[j] * sg;
        }
    }
}

// ---------------------------------------------------------------------------
extern "C" void kernel_launch(void* const* d_in, const int* in_sizes, int n_in,
                              void* d_out, int out_size)
{
    const float* x     = (const float*)d_in[0];
    const int*   mask  = (const int*)  d_in[1];
    const float* noise = (const float*)d_in[2];
    const float* W1    = (const float*)d_in[3];
    const float* b1    = (const float*)d_in[4];
    const float* W2    = (const float*)d_in[5];
    const float* b2    = (const float*)d_in[6];
    float* out = (float*)d_out;

    int write_kpm = ((size_t)out_size >= OUT_OFF + SROWS) ? 1 : 0;

    cudaFuncSetAttribute(k1, cudaFuncAttributeMaxDynamicSharedMemorySize, STAGE_BYTES);
    cudaFuncSetAttribute(k2, cudaFuncAttributeMaxDynamicSharedMemorySize, K2_SMEM);

    k_prep<<<(E_ * H_ + 255) / 256, 256>>>(W1, W2);
    k1<<<dim3(2, (SROWS + 127) / 128), 256, STAGE_BYTES>>>(x, b1);
    k2<<<(SROWS + 127) / 128, 256, K2_SMEM>>>(mask, noise, b2, out, write_kpm);
}

// round 6
// speedup vs baseline: 3.1627x; 1.5180x over previous
#include <cuda_runtime.h>
#include <cuda_bf16.h>
#include <math.h>
#include <stdint.h>

#define C_    16
#define L_    8192
#define E_    512
#define H_    256
#define M_    128
#define KTOP  30
#define SROWS (C_*(L_-1))          // 131056
#define OUT_OFF ((size_t)SROWS * M_)

// Global scratch (allocation-free)
__device__ __align__(16) __nv_bfloat16 g_hhi[(size_t)SROWS * H_];  // h hi plane, 67 MB
__device__ __align__(16) __nv_bfloat16 g_hlo[(size_t)SROWS * H_];  // h lo plane, 67 MB
__device__ __align__(16) __nv_bfloat16 g_w1hi[E_ * H_];            // W1 [k][n] hi
__device__ __align__(16) __nv_bfloat16 g_w1lo[E_ * H_];
__device__ __align__(16) __nv_bfloat16 g_w2hi[H_ * M_];            // W2 [k][n] hi
__device__ __align__(16) __nv_bfloat16 g_w2lo[H_ * M_];

// ---------------------------------------------------------------------------
__device__ __forceinline__ uint32_t smem_u32(const void* p) {
    uint32_t a;
    asm("{ .reg .u64 t; cvta.to.shared.u64 t, %1; cvt.u32.u64 %0, t; }" : "=r"(a) : "l"(p));
    return a;
}
__device__ __forceinline__ void ldsm_x4(uint32_t* r, uint32_t addr) {
    asm volatile("ldmatrix.sync.aligned.m8n8.x4.shared.b16 {%0,%1,%2,%3}, [%4];"
        : "=r"(r[0]), "=r"(r[1]), "=r"(r[2]), "=r"(r[3]) : "r"(addr));
}
__device__ __forceinline__ void ldsm_x4t(uint32_t* r, uint32_t addr) {
    asm volatile("ldmatrix.sync.aligned.m8n8.x4.trans.shared.b16 {%0,%1,%2,%3}, [%4];"
        : "=r"(r[0]), "=r"(r[1]), "=r"(r[2]), "=r"(r[3]) : "r"(addr));
}
__device__ __forceinline__ void mma16816(float* d, const uint32_t* a, const uint32_t* b) {
    asm volatile("mma.sync.aligned.m16n8k16.row.col.f32.bf16.bf16.f32 "
        "{%0,%1,%2,%3}, {%4,%5,%6,%7}, {%8,%9}, {%0,%1,%2,%3};"
        : "+f"(d[0]), "+f"(d[1]), "+f"(d[2]), "+f"(d[3])
        : "r"(a[0]), "r"(a[1]), "r"(a[2]), "r"(a[3]), "r"(b[0]), "r"(b[1]));
}
__device__ __forceinline__ void split1(float v, uint16_t& hi, uint16_t& lo) {
    __nv_bfloat16 h = __float2bfloat16(v);
    hi = __bfloat16_as_ushort(h);
    lo = __bfloat16_as_ushort(__float2bfloat16(v - __bfloat162float(h)));
}
__device__ __forceinline__ void cp16(uint32_t dst, const void* src) {
    asm volatile("cp.async.cg.shared.global [%0], [%1], 16;" :: "r"(dst), "l"(src) : "memory");
}
__device__ __forceinline__ void cp16z(uint32_t dst, const void* src, int sz) {
    asm volatile("cp.async.cg.shared.global [%0], [%1], 16, %2;" :: "r"(dst), "l"(src), "r"(sz) : "memory");
}
#define CP_COMMIT() asm volatile("cp.async.commit_group;" ::: "memory")
#define CP_WAIT0()  asm volatile("cp.async.wait_group 0;" ::: "memory")

// ---------------------------------------------------------------------------
// k_prep: split W1, W2 ([k][n] layout preserved) into bf16 hi/lo
// ---------------------------------------------------------------------------
__global__ void k_prep(const float* __restrict__ W1, const float* __restrict__ W2) {
    int i = blockIdx.x * 256 + threadIdx.x;
    if (i < E_ * H_) {
        uint16_t h, l; split1(W1[i], h, l);
        g_w1hi[i] = __ushort_as_bfloat16(h);
        g_w1lo[i] = __ushort_as_bfloat16(l);
    }
    if (i < H_ * M_) {
        uint16_t h, l; split1(W2[i], h, l);
        g_w2hi[i] = __ushort_as_bfloat16(h);
        g_w2lo[i] = __ushort_as_bfloat16(l);
    }
}

// ---------------------------------------------------------------------------
// GEMM geometry: CTA 128x128, BK=32, 8 warps (2x4), warp 64x32. Double buffered.
// Per-stage: A hi [128][40], A lo [128][40], B hi [32][136], B lo [32][136]
// ---------------------------------------------------------------------------
#define LDA 40
#define LDB 136
#define ASH 0
#define ASL 10240
#define BSH 20480
#define BSL 29184
#define PIPE 37888
#define SMEM_TOT (2 * PIPE)        // 75776

// mma on stage `base`: shared between k1/k2
__device__ __forceinline__ void mma_stage(uint32_t sbase, int lane, int wm, int wn,
                                          float acc[4][4][4]) {
#pragma unroll
    for (int ks = 0; ks < 2; ++ks) {
        const int kk = ks * 16;
        uint32_t bh[2][4], bl[2][4];
        const int brow = kk + (lane & 7) + (((lane >> 3) & 1) << 3);
        const int bcol = wn + ((lane >> 4) << 3);
#pragma unroll
        for (int nn = 0; nn < 2; ++nn) {
            uint32_t off = (uint32_t)(brow * LDB + bcol + nn * 16) * 2;
            ldsm_x4t(bh[nn], sbase + BSH + off);
            ldsm_x4t(bl[nn], sbase + BSL + off);
        }
        const int arow = lane & 15, acol = kk + ((lane >> 4) << 3);
#pragma unroll
        for (int mf = 0; mf < 4; ++mf) {
            uint32_t ah[4], al[4];
            uint32_t off = (uint32_t)((wm + mf * 16 + arow) * LDA + acol) * 2;
            ldsm_x4(ah, sbase + ASH + off);
            ldsm_x4(al, sbase + ASL + off);
#pragma unroll
            for (int nf = 0; nf < 4; ++nf) {
                const uint32_t* bhf = &bh[nf >> 1][(nf & 1) * 2];
                const uint32_t* blf = &bl[nf >> 1][(nf & 1) * 2];
                mma16816(acc[mf][nf], ah, bhf);
                mma16816(acc[mf][nf], al, bhf);
                mma16816(acc[mf][nf], ah, blf);
            }
        }
    }
}

// ---------------------------------------------------------------------------
// k1: h = relu(xs @ W1 + b1), pipelined split-3 bf16 mma.sync
// ---------------------------------------------------------------------------
__global__ __launch_bounds__(256, 2) void k1(const float* __restrict__ x,
                                             const float* __restrict__ b1) {
    extern __shared__ char smem[];
    const uint32_t sb = smem_u32(smem);
    const int tid = threadIdx.x, wid = tid >> 5, lane = tid & 31;
    const int rb = blockIdx.y * 128;
    const int nb = blockIdx.x * 128;
    const int wm = (wid >> 2) * 64, wn = (wid & 3) * 32;

    float acc[4][4][4];
#pragma unroll
    for (int a = 0; a < 4; a++)
#pragma unroll
        for (int b = 0; b < 4; b++)
#pragma unroll
            for (int c = 0; c < 4; c++) acc[a][b][c] = 0.f;

    float4 ar[4];

#define K1_LOADA(IT) do {                                                      \
    _Pragma("unroll")                                                          \
    for (int j = 0; j < 4; ++j) {                                              \
        int i = tid + j * 256; int row = i >> 3, q = i & 7; int r = rb + row;  \
        ar[j] = make_float4(0.f, 0.f, 0.f, 0.f);                               \
        if (r < SROWS) {                                                       \
            int src = r + r / (L_ - 1) + 1;                                    \
            ar[j] = *(const float4*)&x[(size_t)src * E_ + (IT) * 32 + q * 4];  \
        }                                                                      \
    } } while (0)

#define K1_STOREA(S) do {                                                      \
    _Pragma("unroll")                                                          \
    for (int j = 0; j < 4; ++j) {                                              \
        int i = tid + j * 256; int row = i >> 3, q = i & 7;                    \
        uint16_t h0,l0,h1,l1,h2,l2,h3,l3;                                      \
        split1(ar[j].x,h0,l0); split1(ar[j].y,h1,l1);                          \
        split1(ar[j].z,h2,l2); split1(ar[j].w,h3,l3);                          \
        uint2 hv = make_uint2((uint32_t)h0 | ((uint32_t)h1 << 16),             \
                              (uint32_t)h2 | ((uint32_t)h3 << 16));            \
        uint2 lv = make_uint2((uint32_t)l0 | ((uint32_t)l1 << 16),             \
                              (uint32_t)l2 | ((uint32_t)l3 << 16));            \
        *(uint2*)(smem + (S) * PIPE + ASH + row * (LDA*2) + q * 8) = hv;       \
        *(uint2*)(smem + (S) * PIPE + ASL + row * (LDA*2) + q * 8) = lv;       \
    } } while (0)

#define K1_STAGEB(IT, S) do {                                                  \
    _Pragma("unroll")                                                          \
    for (int jj = 0; jj < 2; ++jj) {                                           \
        int i = tid + jj * 256; int k = i >> 4, nq = i & 15;                   \
        size_t gsrc = (size_t)((IT) * 32 + k) * H_ + nb + nq * 8;              \
        cp16(sb + (S) * PIPE + BSH + k * (LDB*2) + nq * 16, &g_w1hi[gsrc]);    \
        cp16(sb + (S) * PIPE + BSL + k * (LDB*2) + nq * 16, &g_w1lo[gsrc]);    \
    } } while (0)

    K1_LOADA(0); K1_STAGEB(0, 0); K1_STOREA(0);
    CP_COMMIT(); CP_WAIT0(); __syncthreads();

    for (int it = 0; it < 16; ++it) {
        const int cur = it & 1, nxt = cur ^ 1;
        if (it < 15) { K1_LOADA(it + 1); K1_STAGEB(it + 1, nxt); CP_COMMIT(); }
        mma_stage(sb + cur * PIPE, lane, wm, wn, acc);
        if (it < 15) { K1_STOREA(nxt); CP_WAIT0(); }
        __syncthreads();
    }

    // epilogue: +b1, relu, split, store to g_hhi/g_hlo
#pragma unroll
    for (int mf = 0; mf < 4; ++mf) {
        int r0 = rb + wm + mf * 16 + (lane >> 2);
#pragma unroll
        for (int half = 0; half < 2; ++half) {
            int r = r0 + half * 8;
            if (r >= SROWS) continue;
#pragma unroll
            for (int nf = 0; nf < 4; ++nf) {
                int c0 = nb + wn + nf * 8 + ((lane & 3) << 1);
                float v0 = fmaxf(acc[mf][nf][half*2+0] + __ldg(&b1[c0]),   0.f);
                float v1 = fmaxf(acc[mf][nf][half*2+1] + __ldg(&b1[c0+1]), 0.f);
                uint16_t h0,l0,h1,l1;
                split1(v0,h0,l0); split1(v1,h1,l1);
                *(uint32_t*)&g_hhi[(size_t)r * H_ + c0] = (uint32_t)h0 | ((uint32_t)h1 << 16);
                *(uint32_t*)&g_hlo[(size_t)r * H_ + c0] = (uint32_t)l0 | ((uint32_t)l1 << 16);
            }
        }
    }
}

// ---------------------------------------------------------------------------
// k2: logits = h @ W2 + b2 (pipelined split-3) + fused gumbel/softmax/top-30
// ---------------------------------------------------------------------------
#define LGS 132
#define K2_SMEM (SMEM_TOT > 128*LGS*4 ? SMEM_TOT : 128*LGS*4)   // 75776

__global__ __launch_bounds__(256, 2) void k2(const int*   __restrict__ mask,
                                             const float* __restrict__ noise,
                                             const float* __restrict__ b2,
                                             float*       __restrict__ out,
                                             int write_kpm) {
    extern __shared__ char smem[];
    const uint32_t sb = smem_u32(smem);
    const int tid = threadIdx.x, wid = tid >> 5, lane = tid & 31;
    const int rb = blockIdx.x * 128;
    const int wm = (wid >> 2) * 64, wn = (wid & 3) * 32;

    float acc[4][4][4];
#pragma unroll
    for (int a = 0; a < 4; a++)
#pragma unroll
        for (int b = 0; b < 4; b++)
#pragma unroll
            for (int c = 0; c < 4; c++) acc[a][b][c] = 0.f;

#define K2_STAGEA(IT, S) do {                                                  \
    _Pragma("unroll")                                                          \
    for (int jj = 0; jj < 2; ++jj) {                                           \
        int i = tid + jj * 256; int row = i >> 2, q = i & 3; int r = rb + row; \
        int ok = (r < SROWS);                                                  \
        size_t gsrc = ok ? ((size_t)r * H_ + (IT) * 32 + q * 8) : 0;           \
        int sz = ok ? 16 : 0;                                                  \
        cp16z(sb + (S) * PIPE + ASH + row * (LDA*2) + q * 16, &g_hhi[gsrc], sz);\
        cp16z(sb + (S) * PIPE + ASL + row * (LDA*2) + q * 16, &g_hlo[gsrc], sz);\
    } } while (0)

#define K2_STAGEB(IT, S) do {                                                  \
    _Pragma("unroll")                                                          \
    for (int jj = 0; jj < 2; ++jj) {                                           \
        int i = tid + jj * 256; int k = i >> 4, nq = i & 15;                   \
        size_t gsrc = (size_t)((IT) * 32 + k) * M_ + nq * 8;                   \
        cp16(sb + (S) * PIPE + BSH + k * (LDB*2) + nq * 16, &g_w2hi[gsrc]);    \
        cp16(sb + (S) * PIPE + BSL + k * (LDB*2) + nq * 16, &g_w2lo[gsrc]);    \
    } } while (0)

    K2_STAGEA(0, 0); K2_STAGEB(0, 0);
    CP_COMMIT(); CP_WAIT0(); __syncthreads();

    for (int it = 0; it < 8; ++it) {
        const int cur = it & 1, nxt = cur ^ 1;
        if (it < 7) { K2_STAGEA(it + 1, nxt); K2_STAGEB(it + 1, nxt); CP_COMMIT(); }
        mma_stage(sb + cur * PIPE, lane, wm, wn, acc);
        if (it < 7) CP_WAIT0();
        __syncthreads();
    }

    // logits (+b2) -> smem
    float* lg = (float*)smem;
#pragma unroll
    for (int mf = 0; mf < 4; ++mf) {
        int rl0 = wm + mf * 16 + (lane >> 2);
#pragma unroll
        for (int half = 0; half < 2; ++half) {
            int rl = rl0 + half * 8;
#pragma unroll
            for (int nf = 0; nf < 4; ++nf) {
                int c0 = wn + nf * 8 + ((lane & 3) << 1);
                lg[rl * LGS + c0]     = acc[mf][nf][half*2+0] + __ldg(&b2[c0]);
                lg[rl * LGS + c0 + 1] = acc[mf][nf][half*2+1] + __ldg(&b2[c0+1]);
            }
        }
    }
    __syncthreads();

    // fused epilogue: warp wid handles rows wid*16 .. +15
    for (int i = 0; i < 16; ++i) {
        int rl = wid * 16 + i;
        int r = rb + rl;
        if (r >= SROWS) continue;

        int cidx = r / (L_ - 1);
        int km = mask[r + cidx + 1];
        if (write_kpm && lane == 0) out[OUT_OFF + r] = km ? 1.0f : 0.0f;
        if (km) {
#pragma unroll
            for (int j = 0; j < 4; ++j) out[(size_t)r * M_ + lane + 32 * j] = 0.0f;
            continue;
        }

        float z[4];
#pragma unroll
        for (int j = 0; j < 4; ++j) {
            float u = noise[(size_t)r * M_ + lane + 32 * j];
            float inner = logf(u + 1e-20f);
            float g = -__logf(-inner + 1e-20f);
            z[j] = lg[rl * LGS + lane + 32 * j] + g;
        }
        float mx = fmaxf(fmaxf(z[0], z[1]), fmaxf(z[2], z[3]));
#pragma unroll
        for (int s = 16; s; s >>= 1) mx = fmaxf(mx, __shfl_xor_sync(0xffffffffu, mx, s));
        float p[4], ssum = 0.f;
#pragma unroll
        for (int j = 0; j < 4; ++j) { p[j] = __expf(z[j] - mx); ssum += p[j]; }
#pragma unroll
        for (int s = 16; s; s >>= 1) ssum += __shfl_xor_sync(0xffffffffu, ssum, s);
        float inv = 1.0f / ssum;
#pragma unroll
        for (int j = 0; j < 4; ++j) p[j] *= inv;

        // exact 30th-largest via bit-pattern bisection
        unsigned lo = 0u, hi = 0x3F800000u;
        for (int itb = 0; itb < 31; ++itb) {
            unsigned mid = lo + ((hi - lo + 1) >> 1);
            float t = __uint_as_float(mid);
            int cgt = (p[0] >= t) + (p[1] >= t) + (p[2] >= t) + (p[3] >= t);
            int tot = __reduce_add_sync(0xffffffffu, cgt);
            if (tot >= KTOP) lo = mid; else hi = mid - 1;
        }
        float th = __uint_as_float(lo);

#pragma unroll
        for (int j = 0; j < 4; ++j) {
            float sg = 1.0f / (1.0f + __expf((th - p[j]) * 100.0f));
            out[(size_t)r * M_ + lane + 32 * j] = p[j] * sg;
        }
    }
}

// ---------------------------------------------------------------------------
extern "C" void kernel_launch(void* const* d_in, const int* in_sizes, int n_in,
                              void* d_out, int out_size)
{
    const float* x     = (const float*)d_in[0];
    const int*   mask  = (const int*)  d_in[1];
    const float* noise = (const float*)d_in[2];
    const float* W1    = (const float*)d_in[3];
    const float* b1    = (const float*)d_in[4];
    const float* W2    = (const float*)d_in[5];
    const float* b2    = (const float*)d_in[6];
    float* out = (float*)d_out;

    int write_kpm = ((size_t)out_size >= OUT_OFF + SROWS) ? 1 : 0;

    cudaFuncSetAttribute(k1, cudaFuncAttributeMaxDynamicSharedMemorySize, SMEM_TOT);
    cudaFuncSetAttribute(k2, cudaFuncAttributeMaxDynamicSharedMemorySize, K2_SMEM);

    k_prep<<<(E_ * H_ + 255) / 256, 256>>>(W1, W2);
    k1<<<dim3(2, (SROWS + 127) / 128), 256, SMEM_TOT>>>(x, b1);
    k2<<<(SROWS + 127) / 128, 256, K2_SMEM>>>(mask, noise, b2, out, write_kpm);
}

// round 8
// speedup vs baseline: 3.1790x; 1.0052x over previous
#include <cuda_runtime.h>
#include <cuda_bf16.h>
#include <math.h>
#include <stdint.h>

#define C_    16
#define L_    8192
#define E_    512
#define H_    256
#define M_    128
#define KTOP  30
#define SROWS (C_*(L_-1))          // 131056
#define OUT_OFF ((size_t)SROWS * M_)

// Global scratch (allocation-free)
__device__ __align__(16) __nv_bfloat16 g_hhi[(size_t)SROWS * H_];  // h hi plane, 67 MB
__device__ __align__(16) __nv_bfloat16 g_hlo[(size_t)SROWS * H_];  // h lo plane, 67 MB
__device__ __align__(16) __nv_bfloat16 g_w1hi[E_ * H_];            // W1 [k][n] hi
__device__ __align__(16) __nv_bfloat16 g_w1lo[E_ * H_];
__device__ __align__(16) __nv_bfloat16 g_w2hi[H_ * M_];            // W2 [k][n] hi
__device__ __align__(16) __nv_bfloat16 g_w2lo[H_ * M_];

// ---------------------------------------------------------------------------
__device__ __forceinline__ uint32_t smem_u32(const void* p) {
    uint32_t a;
    asm("{ .reg .u64 t; cvta.to.shared.u64 t, %1; cvt.u32.u64 %0, t; }" : "=r"(a) : "l"(p));
    return a;
}
__device__ __forceinline__ void ldsm_x4(uint32_t* r, uint32_t addr) {
    asm volatile("ldmatrix.sync.aligned.m8n8.x4.shared.b16 {%0,%1,%2,%3}, [%4];"
        : "=r"(r[0]), "=r"(r[1]), "=r"(r[2]), "=r"(r[3]) : "r"(addr));
}
__device__ __forceinline__ void ldsm_x4t(uint32_t* r, uint32_t addr) {
    asm volatile("ldmatrix.sync.aligned.m8n8.x4.trans.shared.b16 {%0,%1,%2,%3}, [%4];"
        : "=r"(r[0]), "=r"(r[1]), "=r"(r[2]), "=r"(r[3]) : "r"(addr));
}
__device__ __forceinline__ void mma16816(float* d, const uint32_t* a, const uint32_t* b) {
    asm volatile("mma.sync.aligned.m16n8k16.row.col.f32.bf16.bf16.f32 "
        "{%0,%1,%2,%3}, {%4,%5,%6,%7}, {%8,%9}, {%0,%1,%2,%3};"
        : "+f"(d[0]), "+f"(d[1]), "+f"(d[2]), "+f"(d[3])
        : "r"(a[0]), "r"(a[1]), "r"(a[2]), "r"(a[3]), "r"(b[0]), "r"(b[1]));
}
__device__ __forceinline__ void split1(float v, uint16_t& hi, uint16_t& lo) {
    __nv_bfloat16 h = __float2bfloat16(v);
    hi = __bfloat16_as_ushort(h);
    lo = __bfloat16_as_ushort(__float2bfloat16(v - __bfloat162float(h)));
}
__device__ __forceinline__ void cp16(uint32_t dst, const void* src) {
    asm volatile("cp.async.cg.shared.global [%0], [%1], 16;" :: "r"(dst), "l"(src) : "memory");
}
__device__ __forceinline__ void cp16z(uint32_t dst, const void* src, int sz) {
    asm volatile("cp.async.cg.shared.global [%0], [%1], 16, %2;" :: "r"(dst), "l"(src), "r"(sz) : "memory");
}
#define CP_COMMIT() asm volatile("cp.async.commit_group;" ::: "memory")
#define CP_WAIT0()  asm volatile("cp.async.wait_group 0;" ::: "memory")

// ---------------------------------------------------------------------------
// k_prep: split W1, W2 ([k][n] layout preserved) into bf16 hi/lo
// ---------------------------------------------------------------------------
__global__ void k_prep(const float* __restrict__ W1, const float* __restrict__ W2) {
    int i = blockIdx.x * 256 + threadIdx.x;
    if (i < E_ * H_) {
        uint16_t h, l; split1(W1[i], h, l);
        g_w1hi[i] = __ushort_as_bfloat16(h);
        g_w1lo[i] = __ushort_as_bfloat16(l);
    }
    if (i < H_ * M_) {
        uint16_t h, l; split1(W2[i], h, l);
        g_w2hi[i] = __ushort_as_bfloat16(h);
        g_w2lo[i] = __ushort_as_bfloat16(l);
    }
}

// ---------------------------------------------------------------------------
// GEMM geometry: CTA 128x128, BK=32, 8 warps (2x4), warp 64x32. Double buffered.
// ---------------------------------------------------------------------------
#define LDA 40
#define LDB 136
#define ASH 0
#define ASL 10240
#define BSH 20480
#define BSL 29184
#define PIPE 37888
#define SMEM_TOT (2 * PIPE)        // 75776

// mma on one stage. Term-major ordering: for each A-row-block (mf), issue all
// four nf-tiles of term hh, then all of lh, then all of hl -> dependent-mma
// distance 4 on every accumulator (was 1).
__device__ __forceinline__ void mma_stage(uint32_t sbase, int lane, int wm, int wn,
                                          float acc[4][4][4]) {
#pragma unroll
    for (int ks = 0; ks < 2; ++ks) {
        const int kk = ks * 16;
        uint32_t bh[2][4], bl[2][4];
        const int brow = kk + (lane & 7) + (((lane >> 3) & 1) << 3);
        const int bcol = wn + ((lane >> 4) << 3);
#pragma unroll
        for (int nn = 0; nn < 2; ++nn) {
            uint32_t off = (uint32_t)(brow * LDB + bcol + nn * 16) * 2;
            ldsm_x4t(bh[nn], sbase + BSH + off);
            ldsm_x4t(bl[nn], sbase + BSL + off);
        }
        const int arow = lane & 15, acol = kk + ((lane >> 4) << 3);
#pragma unroll
        for (int mf = 0; mf < 4; ++mf) {
            uint32_t ah[4], al[4];
            uint32_t off = (uint32_t)((wm + mf * 16 + arow) * LDA + acol) * 2;
            ldsm_x4(ah, sbase + ASH + off);
            ldsm_x4(al, sbase + ASL + off);
#pragma unroll
            for (int nf = 0; nf < 4; ++nf)
                mma16816(acc[mf][nf], ah, &bh[nf >> 1][(nf & 1) * 2]);
#pragma unroll
            for (int nf = 0; nf < 4; ++nf)
                mma16816(acc[mf][nf], al, &bh[nf >> 1][(nf & 1) * 2]);
#pragma unroll
            for (int nf = 0; nf < 4; ++nf)
                mma16816(acc[mf][nf], ah, &bl[nf >> 1][(nf & 1) * 2]);
        }
    }
}

// ---------------------------------------------------------------------------
// k1: h = relu(xs @ W1 + b1), pipelined split-3 bf16 mma.sync
// ---------------------------------------------------------------------------
__global__ __launch_bounds__(256, 2) void k1(const float* __restrict__ x,
                                             const float* __restrict__ b1) {
    extern __shared__ char smem[];
    const uint32_t sb = smem_u32(smem);
    const int tid = threadIdx.x, wid = tid >> 5, lane = tid & 31;
    const int rb = blockIdx.y * 128;
    const int nb = blockIdx.x * 128;
    const int wm = (wid >> 2) * 64, wn = (wid & 3) * 32;

    float acc[4][4][4];
#pragma unroll
    for (int a = 0; a < 4; a++)
#pragma unroll
        for (int b = 0; b < 4; b++)
#pragma unroll
            for (int c = 0; c < 4; c++) acc[a][b][c] = 0.f;

    float4 ar[4];

#define K1_LOADA(IT) do {                                                      \
    _Pragma("unroll")                                                          \
    for (int j = 0; j < 4; ++j) {                                              \
        int i = tid + j * 256; int row = i >> 3, q = i & 7; int r = rb + row;  \
        ar[j] = make_float4(0.f, 0.f, 0.f, 0.f);                               \
        if (r < SROWS) {                                                       \
            int src = r + r / (L_ - 1) + 1;                                    \
            ar[j] = *(const float4*)&x[(size_t)src * E_ + (IT) * 32 + q * 4];  \
        }                                                                      \
    } } while (0)

#define K1_STOREA(S) do {                                                      \
    _Pragma("unroll")                                                          \
    for (int j = 0; j < 4; ++j) {                                              \
        int i = tid + j * 256; int row = i >> 3, q = i & 7;                    \
        uint16_t h0,l0,h1,l1,h2,l2,h3,l3;                                      \
        split1(ar[j].x,h0,l0); split1(ar[j].y,h1,l1);                          \
        split1(ar[j].z,h2,l2); split1(ar[j].w,h3,l3);                          \
        uint2 hv = make_uint2((uint32_t)h0 | ((uint32_t)h1 << 16),             \
                              (uint32_t)h2 | ((uint32_t)h3 << 16));            \
        uint2 lv = make_uint2((uint32_t)l0 | ((uint32_t)l1 << 16),             \
                              (uint32_t)l2 | ((uint32_t)l3 << 16));            \
        *(uint2*)(smem + (S) * PIPE + ASH + row * (LDA*2) + q * 8) = hv;       \
        *(uint2*)(smem + (S) * PIPE + ASL + row * (LDA*2) + q * 8) = lv;       \
    } } while (0)

#define K1_STAGEB(IT, S) do {                                                  \
    _Pragma("unroll")                                                          \
    for (int jj = 0; jj < 2; ++jj) {                                           \
        int i = tid + jj * 256; int k = i >> 4, nq = i & 15;                   \
        size_t gsrc = (size_t)((IT) * 32 + k) * H_ + nb + nq * 8;              \
        cp16(sb + (S) * PIPE + BSH + k * (LDB*2) + nq * 16, &g_w1hi[gsrc]);    \
        cp16(sb + (S) * PIPE + BSL + k * (LDB*2) + nq * 16, &g_w1lo[gsrc]);    \
    } } while (0)

    K1_LOADA(0); K1_STAGEB(0, 0); K1_STOREA(0);
    CP_COMMIT(); CP_WAIT0(); __syncthreads();

    for (int it = 0; it < 16; ++it) {
        const int cur = it & 1, nxt = cur ^ 1;
        if (it < 15) { K1_LOADA(it + 1); K1_STAGEB(it + 1, nxt); CP_COMMIT(); }
        mma_stage(sb + cur * PIPE, lane, wm, wn, acc);
        if (it < 15) { K1_STOREA(nxt); CP_WAIT0(); }
        __syncthreads();
    }

    // epilogue: +b1, relu, split, store to g_hhi/g_hlo
#pragma unroll
    for (int mf = 0; mf < 4; ++mf) {
        int r0 = rb + wm + mf * 16 + (lane >> 2);
#pragma unroll
        for (int half = 0; half < 2; ++half) {
            int r = r0 + half * 8;
            if (r >= SROWS) continue;
#pragma unroll
            for (int nf = 0; nf < 4; ++nf) {
                int c0 = nb + wn + nf * 8 + ((lane & 3) << 1);
                float v0 = fmaxf(acc[mf][nf][half*2+0] + __ldg(&b1[c0]),   0.f);
                float v1 = fmaxf(acc[mf][nf][half*2+1] + __ldg(&b1[c0+1]), 0.f);
                uint16_t h0,l0,h1,l1;
                split1(v0,h0,l0); split1(v1,h1,l1);
                *(uint32_t*)&g_hhi[(size_t)r * H_ + c0] = (uint32_t)h0 | ((uint32_t)h1 << 16);
                *(uint32_t*)&g_hlo[(size_t)r * H_ + c0] = (uint32_t)l0 | ((uint32_t)l1 << 16);
            }
        }
    }
}

// ---------------------------------------------------------------------------
// k2: logits = h @ W2 + b2 (pipelined split-3) + fused gumbel/softmax/top-30
// ---------------------------------------------------------------------------
#define LGS 132
#define K2_SMEM (SMEM_TOT > 128*LGS*4 ? SMEM_TOT : 128*LGS*4)   // 75776

__global__ __launch_bounds__(256, 2) void k2(const int*   __restrict__ mask,
                                             const float* __restrict__ noise,
                                             const float* __restrict__ b2,
                                             float*       __restrict__ out,
                                             int write_kpm) {
    extern __shared__ char smem[];
    const uint32_t sb = smem_u32(smem);
    const int tid = threadIdx.x, wid = tid >> 5, lane = tid & 31;
    const int rb = blockIdx.x * 128;
    const int wm = (wid >> 2) * 64, wn = (wid & 3) * 32;

    float acc[4][4][4];
#pragma unroll
    for (int a = 0; a < 4; a++)
#pragma unroll
        for (int b = 0; b < 4; b++)
#pragma unroll
            for (int c = 0; c < 4; c++) acc[a][b][c] = 0.f;

#define K2_STAGEA(IT, S) do {                                                  \
    _Pragma("unroll")                                                          \
    for (int jj = 0; jj < 2; ++jj) {                                           \
        int i = tid + jj * 256; int row = i >> 2, q = i & 3; int r = rb + row; \
        int ok = (r < SROWS);                                                  \
        size_t gsrc = ok ? ((size_t)r * H_ + (IT) * 32 + q * 8) : 0;           \
        int sz = ok ? 16 : 0;                                                  \
        cp16z(sb + (S) * PIPE + ASH + row * (LDA*2) + q * 16, &g_hhi[gsrc], sz);\
        cp16z(sb + (S) * PIPE + ASL + row * (LDA*2) + q * 16, &g_hlo[gsrc], sz);\
    } } while (0)

#define K2_STAGEB(IT, S) do {                                                  \
    _Pragma("unroll")                                                          \
    for (int jj = 0; jj < 2; ++jj) {                                           \
        int i = tid + jj * 256; int k = i >> 4, nq = i & 15;                   \
        size_t gsrc = (size_t)((IT) * 32 + k) * M_ + nq * 8;                   \
        cp16(sb + (S) * PIPE + BSH + k * (LDB*2) + nq * 16, &g_w2hi[gsrc]);    \
        cp16(sb + (S) * PIPE + BSL + k * (LDB*2) + nq * 16, &g_w2lo[gsrc]);    \
    } } while (0)

    K2_STAGEA(0, 0); K2_STAGEB(0, 0);
    CP_COMMIT(); CP_WAIT0(); __syncthreads();

    for (int it = 0; it < 8; ++it) {
        const int cur = it & 1, nxt = cur ^ 1;
        if (it < 7) { K2_STAGEA(it + 1, nxt); K2_STAGEB(it + 1, nxt); CP_COMMIT(); }
        mma_stage(sb + cur * PIPE, lane, wm, wn, acc);
        if (it < 7) CP_WAIT0();
        __syncthreads();
    }

    // logits (+b2) -> smem
    float* lg = (float*)smem;
#pragma unroll
    for (int mf = 0; mf < 4; ++mf) {
        int rl0 = wm + mf * 16 + (lane >> 2);
#pragma unroll
        for (int half = 0; half < 2; ++half) {
            int rl = rl0 + half * 8;
#pragma unroll
            for (int nf = 0; nf < 4; ++nf) {
                int c0 = wn + nf * 8 + ((lane & 3) << 1);
                lg[rl * LGS + c0]     = acc[mf][nf][half*2+0] + __ldg(&b2[c0]);
                lg[rl * LGS + c0 + 1] = acc[mf][nf][half*2+1] + __ldg(&b2[c0+1]);
            }
        }
    }
    __syncthreads();

    // fused epilogue: warp wid handles rows wid*16 .. +15
    for (int i = 0; i < 16; ++i) {
        int rl = wid * 16 + i;
        int r = rb + rl;
        if (r >= SROWS) continue;

        int cidx = r / (L_ - 1);
        int km = mask[r + cidx + 1];
        if (write_kpm && lane == 0) out[OUT_OFF + r] = km ? 1.0f : 0.0f;
        if (km) {
#pragma unroll
            for (int j = 0; j < 4; ++j) out[(size_t)r * M_ + lane + 32 * j] = 0.0f;
            continue;
        }

        float z[4];
#pragma unroll
        for (int j = 0; j < 4; ++j) {
            float u = noise[(size_t)r * M_ + lane + 32 * j];
            float inner = logf(u + 1e-20f);
            float g = -__logf(-inner + 1e-20f);
            z[j] = lg[rl * LGS + lane + 32 * j] + g;
        }
        float mx = fmaxf(fmaxf(z[0], z[1]), fmaxf(z[2], z[3]));
#pragma unroll
        for (int s = 16; s; s >>= 1) mx = fmaxf(mx, __shfl_xor_sync(0xffffffffu, mx, s));
        float p[4], ssum = 0.f;
#pragma unroll
        for (int j = 0; j < 4; ++j) { p[j] = __expf(z[j] - mx); ssum += p[j]; }
#pragma unroll
        for (int s = 16; s; s >>= 1) ssum += __shfl_xor_sync(0xffffffffu, ssum, s);
        float inv = 1.0f / ssum;
#pragma unroll
        for (int j = 0; j < 4; ++j) p[j] *= inv;

        // exact 30th-largest via bit-pattern bisection
        unsigned lo = 0u, hi = 0x3F800000u;
        for (int itb = 0; itb < 31; ++itb) {
            unsigned mid = lo + ((hi - lo + 1) >> 1);
            float t = __uint_as_float(mid);
            int cgt = (p[0] >= t) + (p[1] >= t) + (p[2] >= t) + (p[3] >= t);
            int tot = __reduce_add_sync(0xffffffffu, cgt);
            if (tot >= KTOP) lo = mid; else hi = mid - 1;
        }
        float th = __uint_as_float(lo);

#pragma unroll
        for (int j = 0; j < 4; ++j) {
            float sg = 1.0f / (1.0f + __expf((th - p[j]) * 100.0f));
            out[(size_t)r * M_ + lane + 32 * j] = p[j] * sg;
        }
    }
}

// ---------------------------------------------------------------------------
extern "C" void kernel_launch(void* const* d_in, const int* in_sizes, int n_in,
                              void* d_out, int out_size)
{
    const float* x     = (const float*)d_in[0];
    const int*   mask  = (const int*)  d_in[1];
    const float* noise = (const float*)d_in[2];
    const float* W1    = (const float*)d_in[3];
    const float* b1    = (const float*)d_in[4];
    const float* W2    = (const float*)d_in[5];
    const float* b2    = (const float*)d_in[6];
    float* out = (float*)d_out;

    int write_kpm = ((size_t)out_size >= OUT_OFF + SROWS) ? 1 : 0;

    cudaFuncSetAttribute(k1, cudaFuncAttributeMaxDynamicSharedMemorySize, SMEM_TOT);
    cudaFuncSetAttribute(k2, cudaFuncAttributeMaxDynamicSharedMemorySize, K2_SMEM);

    k_prep<<<(E_ * H_ + 255) / 256, 256>>>(W1, W2);
    k1<<<dim3(2, (SROWS + 127) / 128), 256, SMEM_TOT>>>(x, b1);
    k2<<<(SROWS + 127) / 128, 256, K2_SMEM>>>(mask, noise, b2, out, write_kpm);
}